// round 5
// baseline (speedup 1.0000x reference)
#include <cuda_runtime.h>
#include <cstdint>

#define DD 256
#define NA_MAX (64*256)
#define NR_MAX (512*256)

// ---------------- scratch state (device globals; no allocation) ----------------
__device__ __align__(16) float gA [NA_MAX*DD];        // state, raw
__device__ __align__(16) float gR [NR_MAX*DD];
__device__ __align__(16) float gAq[NA_MAX*DD];
__device__ __align__(16) float gAk[NA_MAX*DD];
__device__ __align__(16) float gAv[NA_MAX*DD];
__device__ __align__(16) float gRq[NR_MAX*DD];
__device__ __align__(16) float gRk[NR_MAX*DD];
__device__ __align__(16) float gRv[NR_MAX*DD];
__device__ __align__(16) float gAp [NA_MAX*DD*2];     // state, permuted hi/lo
__device__ __align__(16) float gRp [NR_MAX*DD*2];
__device__ __align__(16) float gTAp[NA_MAX*DD*2];     // attn out (and init input), permuted hi/lo
__device__ __align__(16) float gTRp[NR_MAX*DD*2];
__device__ __align__(16) float gWp [10*DD*DD*2];      // weights, permuted hi/lo
__device__ float gInvA[NA_MAX];
__device__ float gInvR[NR_MAX];

__device__ __forceinline__ float leaky_f(float x) { return x >= 0.f ? x : 0.1f * x; }
__device__ __forceinline__ float sigmoid_f(float x) {
    return __fdividef(1.f, 1.f + __expf(-x));
}
__device__ __forceinline__ float to_tf32(float x) {
    uint32_t u;
    asm("cvt.rna.tf32.f32 %0, %1;" : "=r"(u) : "f"(x));
    return __uint_as_float(u);
}
__device__ __forceinline__ void split_tf32(float x, float& hi, float& lo) {
    uint32_t u;
    asm("cvt.rna.tf32.f32 %0, %1;" : "=r"(u) : "f"(x));
    hi = __uint_as_float(u);
    float r = x - hi;
    uint32_t v;
    asm("cvt.rna.tf32.f32 %0, %1;" : "=r"(v) : "f"(r));
    lo = __uint_as_float(v);
}
__device__ __forceinline__ void mma_tf32(float* d, const uint32_t* a, const uint32_t* b) {
    asm volatile(
        "mma.sync.aligned.m16n8k8.row.col.f32.tf32.tf32.f32 "
        "{%0,%1,%2,%3}, {%4,%5,%6,%7}, {%8,%9}, {%0,%1,%2,%3};\n"
        : "+f"(d[0]), "+f"(d[1]), "+f"(d[2]), "+f"(d[3])
        : "r"(a[0]), "r"(a[1]), "r"(a[2]), "r"(a[3]), "r"(b[0]), "r"(b[1]));
}
__device__ __forceinline__ uint32_t smem_u32(const void* p) {
    return (uint32_t)__cvta_generic_to_shared(p);
}
__device__ __forceinline__ void cp16(uint32_t s, const void* g) {
    asm volatile("cp.async.cg.shared.global [%0], [%1], 16;\n" :: "r"(s), "l"(g));
}
__device__ __forceinline__ void cp_commit() { asm volatile("cp.async.commit_group;\n"); }
template <int N> __device__ __forceinline__ void cp_wait() {
    asm volatile("cp.async.wait_group %0;\n" :: "n"(N));
}

// Permuted X layout: element (r,k) hi at
//   ((r>>7)*8 + (k>>5))*8192 + (((k>>3)&3)*8 + ((r&127)>>4))*32*8 + ((r&7)*4 + (k&3))*8 + e
// with e = ((r>>3)&1) + 2*((k>>2)&1); lo at +4.  (64KB-per-128-row-tile chunks of 32KB/k-tile)
__device__ __forceinline__ size_t xperm_addr(int r, int k) {
    int rowtile = r >> 7, ktile = k >> 5;
    int kk = (k >> 3) & 3, wmf = (r & 127) >> 4;
    int lane = (r & 7) * 4 + (k & 3);
    int e = ((r >> 3) & 1) + 2 * ((k >> 2) & 1);
    return ((size_t)(rowtile * 8 + ktile)) * 8192 + (size_t)((kk * 8 + wmf) * 32 + lane) * 8 + e;
}

// ---------------- per-row 1/count scales ----------------
__global__ void fill_inv_kernel(const int* __restrict__ lig, const int* __restrict__ res) {
    int b = blockIdx.x;
    int as = lig[2*b], ac = lig[2*b+1];
    int rs = res[2*b], rc = res[2*b+1];
    float ia = 1.f / (float)rc;
    float ir = 1.f / (float)ac;
    for (int i = threadIdx.x; i < ac; i += blockDim.x) gInvA[as + i] = ia;
    for (int i = threadIdx.x; i < rc; i += blockDim.x) gInvR[rs + i] = ir;
}

// ---------------- weight presplit + permute (fragment-major) ----------------
// Layout: [slot][coltile4][ktile8] 4096-float chunks of [kk4][nf8][lane32][{bh0,bh1,bl0,bl1}]
struct WIn { const float* w[10]; };
__global__ void presplit_w_kernel(WIn win, float* __restrict__ wp) {
    int i = blockIdx.x * 256 + threadIdx.x;
    if (i >= 10 * DD * DD) return;
    int s = i >> 16, rem = i & 65535;
    int k = rem >> 8, n = rem & 255;
    float h, l;
    split_tf32(win.w[s][rem], h, l);
    int coltile = n >> 6, nf8 = (n >> 3) & 7, lq = n & 7;
    int ktile = k >> 5, kk = (k >> 3) & 3, lr = k & 3, khalf = (k >> 2) & 1;
    int lane = lq * 4 + lr;
    size_t base = ((size_t)((s * 4 + coltile) * 8 + ktile)) * 4096
                + (size_t)((kk * 8 + nf8) * 32 + lane) * 4;
    wp[base + khalf] = h;
    wp[base + 2 + khalf] = l;
}

// ---------------- split+permute a raw row-major X into fragment-major hi/lo ----------------
__global__ void splitperm_x_kernel(const float* __restrict__ src, float* __restrict__ dst, int M) {
    int i = blockIdx.x * 256 + threadIdx.x;
    if (i >= M * DD) return;
    int r = i >> 8, k = i & 255;
    float h, l;
    split_tf32(src[i], h, l);
    size_t a = xperm_addr(r, k);
    dst[a] = h;
    dst[a + 4] = l;
}

// ---------------- fused 3xTF32 pipelined GEMM (all operands pre-split/permuted) ----------------
// grid = (NW*4 variants, aTiles+rTiles).  MODE 0: C=XW ; 1: C=leaky(XW) ; 2: C=leaky(XW)*scale+base
struct GArgs {
    const float* Xp[2];        // permuted-split X
    const float* Wp[2][3];     // permuted-split W (slot base)
    float*       Craw[2][3];   // raw outputs
    float*       Cp[2];        // permuted-split state out (MODE 1/2)
    const float* scale[2];
    const float* base[2];
    int M[2];
    int aTiles;
};

#define G_STAGE (8192 + 4096)          // floats per stage
#define GEMM_SMEM (2*G_STAGE*4)        // 98304 B

template <int MODE>
__global__ void gemm_fused_kernel(GArgs g)
{
    extern __shared__ float smf[];
    const int side = (blockIdx.y >= g.aTiles) ? 1 : 0;
    const int rt = side ? blockIdx.y - g.aTiles : blockIdx.y;
    const int w = blockIdx.x >> 2, coltile = blockIdx.x & 3;
    const int col0 = coltile * 64;
    const int M = g.M[side];
    const int row0 = rt * 128;

    const float* Xp = g.Xp[side] + (size_t)rt * 65536;
    const float* Wp = g.Wp[side][w] + (size_t)coltile * 32768;
    float* C = g.Craw[side][w];

    const int tid = threadIdx.x, lane = tid & 31, warp = tid >> 5;
    const int wm = warp >> 1, wn = warp & 1;
    const int lq = lane >> 2, lr = lane & 3;

    float* sA[2] = { smf,        smf + G_STAGE };
    float* sB[2] = { smf + 8192, smf + G_STAGE + 8192 };

    float acc[2][4][4] = {};

    // stage k-tile 0
    #pragma unroll
    for (int j = 0; j < 8; j++)
        cp16(smem_u32(sA[0] + (tid + 256 * j) * 4), Xp + (size_t)(tid + 256 * j) * 4);
    #pragma unroll
    for (int j = 0; j < 4; j++)
        cp16(smem_u32(sB[0] + (tid + 256 * j) * 4), Wp + (size_t)(tid + 256 * j) * 4);
    cp_commit();

    for (int t = 0; t < 8; t++) {
        int buf = t & 1;
        if (t < 7) {
            const float* Xn = Xp + (size_t)(t + 1) * 8192;
            const float* Wn = Wp + (size_t)(t + 1) * 4096;
            #pragma unroll
            for (int j = 0; j < 8; j++)
                cp16(smem_u32(sA[buf ^ 1] + (tid + 256 * j) * 4), Xn + (size_t)(tid + 256 * j) * 4);
            #pragma unroll
            for (int j = 0; j < 4; j++)
                cp16(smem_u32(sB[buf ^ 1] + (tid + 256 * j) * 4), Wn + (size_t)(tid + 256 * j) * 4);
            cp_commit();
            cp_wait<1>();
        } else {
            cp_wait<0>();
        }
        __syncthreads();

        #pragma unroll
        for (int kk = 0; kk < 4; kk++) {
            float4 ahv[2], alv[2];
            #pragma unroll
            for (int mf = 0; mf < 2; mf++) {
                const float4* ap = (const float4*)(sA[buf] + (size_t)((kk * 8 + wm * 2 + mf) * 32 + lane) * 8);
                ahv[mf] = ap[0];
                alv[mf] = ap[1];
            }
            float4 bv[4];
            #pragma unroll
            for (int nf = 0; nf < 4; nf++)
                bv[nf] = *(const float4*)(sB[buf] + (size_t)((kk * 8 + wn * 4 + nf) * 32 + lane) * 4);

            #pragma unroll
            for (int mf = 0; mf < 2; mf++) {
                const uint32_t* ah = (const uint32_t*)&ahv[mf];
                const uint32_t* al = (const uint32_t*)&alv[mf];
                #pragma unroll
                for (int nf = 0; nf < 4; nf++) {
                    const uint32_t* bq = (const uint32_t*)&bv[nf];
                    uint32_t bh[2] = { bq[0], bq[1] };
                    uint32_t bl[2] = { bq[2], bq[3] };
                    mma_tf32(acc[mf][nf], al, bh);
                    mma_tf32(acc[mf][nf], ah, bl);
                    mma_tf32(acc[mf][nf], ah, bh);
                }
            }
        }
        __syncthreads();
    }

    // ---- epilogue: raw store (+ permuted-split state store for MODE 1/2) ----
    float* Cp = (MODE != 0) ? g.Cp[side] : nullptr;
    #pragma unroll
    for (int mf = 0; mf < 2; mf++) {
        #pragma unroll
        for (int i = 0; i < 4; i++) {
            int r = row0 + wm * 32 + mf * 16 + lq + ((i >= 2) ? 8 : 0);
            if (r >= M) continue;
            float sc = (MODE == 2) ? g.scale[side][r] : 0.f;
            #pragma unroll
            for (int nf = 0; nf < 4; nf++) {
                int c = col0 + wn * 32 + nf * 8 + lr * 2 + (i & 1);
                float v = acc[mf][nf][i];
                if (MODE == 1) v = leaky_f(v);
                if (MODE == 2) v = leaky_f(v) * sc + g.base[side][(size_t)r * DD + c];
                C[(size_t)r * DD + c] = v;
                if (MODE != 0) {
                    float h, l;
                    split_tf32(v, h, l);
                    size_t a = xperm_addr(r, c);
                    Cp[a] = h;
                    Cp[a + 4] = l;
                }
            }
        }
    }
}

// ---------------- mma sigmoid attention, cp.async pipelined, permuted Q ----------------
// Block: (complex b, 64-row query chunk). Output written permuted-split into Op.
#define KV_STR 264
#define SSTR2 40
#define ATT_QP 0
#define ATT_SS 16384
#define ATT_RA (16384 + 64*SSTR2)
#define ATT_RB (ATT_RA + 2*32*KV_STR)
#define ATT_SMEM ((ATT_RB + 2*32*KV_STR) * 4)   // 210944 B

__device__ __forceinline__ void attn_stage_kv(const float* K, const float* V,
                                              float* regKb, float* regVb,
                                              size_t kv0, int t0, int kvc, int tid)
{
    #pragma unroll
    for (int i = 0; i < 8; i++) {
        int idx = tid + 256 * i;
        int row = idx >> 6, ch = idx & 63;
        int gr = t0 + row; if (gr > kvc - 1) gr = kvc - 1;   // clamp: masked later
        cp16(smem_u32(regKb + row * KV_STR + ch * 4), K + (kv0 + gr) * DD + ch * 4);
        cp16(smem_u32(regVb + row * KV_STR + ch * 4), V + (kv0 + gr) * DD + ch * 4);
    }
}

__global__ void attn_mma_kernel(const float* __restrict__ Q, const float* __restrict__ K,
                                const float* __restrict__ V, float* __restrict__ Op,
                                const int* __restrict__ scQ, const int* __restrict__ scKV)
{
    extern __shared__ float smf[];
    float* Qp = smf + ATT_QP;
    float* sS = smf + ATT_SS;
    float* regK[2]; float* regV[2];
    regK[0] = smf + ATT_RA; regV[0] = regK[0] + 32 * KV_STR;
    regK[1] = smf + ATT_RB; regV[1] = regK[1] + 32 * KV_STR;
    float* Qraw = regK[0];

    const int b = blockIdx.x;
    const int qs0 = scQ[2*b], qc = scQ[2*b+1];
    const int kv0i = scKV[2*b], kvc = scKV[2*b+1];
    const int qbeg = blockIdx.y * 64;
    if (qbeg >= qc) return;
    const int qcnt = (qc - qbeg < 64) ? (qc - qbeg) : 64;

    const int tid = threadIdx.x, lane = tid & 31, warp = tid >> 5;
    const int lq = lane >> 2, lr = lane & 3;

    #pragma unroll
    for (int i = 0; i < 16; i++) {
        int idx = tid + 256 * i;
        int row = idx >> 6, ch = idx & 63;
        int gr = qbeg + row; if (gr > qc - 1) gr = qc - 1;
        cp16(smem_u32(Qraw + row * KV_STR + ch * 4), Q + (size_t)(qs0 + gr) * DD + ch * 4);
    }
    cp_commit();
    attn_stage_kv(K, V, regK[1], regV[1], (size_t)kv0i, 0, kvc, tid);
    cp_commit();

    cp_wait<1>();
    __syncthreads();

    {
        int mt = warp >> 1;
        #pragma unroll
        for (int i = 0; i < 16; i++) {
            int kk = (warp & 1) * 16 + i;
            const float* qb = Qraw + (mt * 16 + lq) * KV_STR + kk * 8 + lr;
            float4 v;
            v.x = to_tf32(qb[0]);
            v.y = to_tf32(qb[8 * KV_STR]);
            v.z = to_tf32(qb[4]);
            v.w = to_tf32(qb[8 * KV_STR + 4]);
            *(float4*)(Qp + ((size_t)(mt * 32 + kk) * 32 + lane) * 4) = v;
        }
    }
    __syncthreads();

    float o[4][4][4] = {};
    const int nT = (kvc + 31) >> 5;

    for (int t = 0; t < nT; t++) {
        int buf = (t & 1) ^ 1;
        if (t + 1 < nT) {
            attn_stage_kv(K, V, regK[buf ^ 1], regV[buf ^ 1], (size_t)kv0i, (t + 1) * 32, kvc, tid);
            cp_commit();
            cp_wait<1>();
        } else {
            cp_wait<0>();
        }
        __syncthreads();

        int klim = kvc - t * 32; if (klim > 32) klim = 32;

        {
            const int wm = warp >> 1, wn = warp & 1;
            const int m0 = wm * 16, n0 = wn * 16;
            float s[2][4] = {};
            #pragma unroll 4
            for (int kk = 0; kk < 32; kk++) {
                float4 qv = *(const float4*)(Qp + ((size_t)(wm * 32 + kk) * 32 + lane) * 4);
                uint32_t a[4] = { __float_as_uint(qv.x), __float_as_uint(qv.y),
                                  __float_as_uint(qv.z), __float_as_uint(qv.w) };
                uint32_t bb[2][2];
                #pragma unroll
                for (int nf = 0; nf < 2; nf++) {
                    const float* kp = regK[buf] + (n0 + nf * 8 + lq) * KV_STR + kk * 8 + lr;
                    bb[nf][0] = __float_as_uint(to_tf32(kp[0]));
                    bb[nf][1] = __float_as_uint(to_tf32(kp[4]));
                }
                mma_tf32(s[0], a, bb[0]);
                mma_tf32(s[1], a, bb[1]);
            }
            #pragma unroll
            for (int nf = 0; nf < 2; nf++)
                #pragma unroll
                for (int e = 0; e < 4; e++) {
                    int row = m0 + lq + ((e >= 2) ? 8 : 0);
                    int col = n0 + nf * 8 + lr * 2 + (e & 1);
                    float v = (col < klim) ? sigmoid_f(s[nf][e]) : 0.f;
                    sS[row * SSTR2 + col] = to_tf32(v);
                }
        }
        __syncthreads();

        {
            const int n0 = warp * 32;
            #pragma unroll
            for (int ks = 0; ks < 4; ks++) {
                uint32_t a[4][4], bb[4][2];
                #pragma unroll
                for (int mf = 0; mf < 4; mf++) {
                    const float* sp = sS + (mf * 16 + lq) * SSTR2 + ks * 8 + lr;
                    a[mf][0] = __float_as_uint(sp[0]);
                    a[mf][1] = __float_as_uint(sp[8 * SSTR2]);
                    a[mf][2] = __float_as_uint(sp[4]);
                    a[mf][3] = __float_as_uint(sp[8 * SSTR2 + 4]);
                }
                #pragma unroll
                for (int nf = 0; nf < 4; nf++) {
                    const float* vp = regV[buf] + (ks * 8 + lr) * KV_STR + n0 + nf * 8 + lq;
                    bb[nf][0] = __float_as_uint(to_tf32(vp[0]));
                    bb[nf][1] = __float_as_uint(to_tf32(vp[4 * KV_STR]));
                }
                #pragma unroll
                for (int mf = 0; mf < 4; mf++)
                    #pragma unroll
                    for (int nf = 0; nf < 4; nf++)
                        mma_tf32(o[mf][nf], a[mf], bb[nf]);
            }
        }
        __syncthreads();
    }

    // ---- store O permuted-split (consumed only by the output GEMM) ----
    const int n0 = warp * 32;
    #pragma unroll
    for (int mf = 0; mf < 4; mf++)
        #pragma unroll
        for (int e = 0; e < 4; e++) {
            int row = mf * 16 + lq + ((e >= 2) ? 8 : 0);
            if (row >= qcnt) continue;
            int rg = qs0 + qbeg + row;
            #pragma unroll
            for (int nf = 0; nf < 4; nf++) {
                int k = n0 + nf * 8 + lr * 2 + (e & 1);
                float h, l;
                split_tf32(o[mf][nf][e], h, l);
                size_t a = xperm_addr(rg, k);
                Op[a] = h;
                Op[a + 4] = l;
            }
        }
}

// ---------------- final output: concat(A_flat, R_flat) ----------------
__global__ void copy_out_kernel(float* __restrict__ out, int nA, int nR) {
    size_t na4 = (size_t)nA * DD / 4;
    size_t tot = (size_t)(nA + nR) * DD / 4;
    const float4* a4 = (const float4*)gA;
    const float4* r4 = (const float4*)gR;
    for (size_t i = blockIdx.x * (size_t)blockDim.x + threadIdx.x; i < tot;
         i += (size_t)gridDim.x * blockDim.x) {
        ((float4*)out)[i] = (i < na4) ? a4[i] : r4[i - na4];
    }
}

// ---------------- host launch ----------------
extern "C" void kernel_launch(void* const* d_in, const int* in_sizes, int n_in,
                              void* d_out, int out_size) {
    const float* fatoms = (const float*)d_in[0];
    const float* fres   = (const float*)d_in[1];
    const int* lig = (const int*)d_in[12];
    const int* res = (const int*)d_in[13];

    int nA = in_sizes[0] / DD;
    int nR = in_sizes[1] / DD;

    float *pA, *pR, *pAq, *pAk, *pAv, *pRq, *pRk, *pRv;
    float *pAp, *pRp, *pTAp, *pTRp, *pWp, *pInvA, *pInvR;
    cudaGetSymbolAddress((void**)&pA,  gA);
    cudaGetSymbolAddress((void**)&pR,  gR);
    cudaGetSymbolAddress((void**)&pAq, gAq);
    cudaGetSymbolAddress((void**)&pAk, gAk);
    cudaGetSymbolAddress((void**)&pAv, gAv);
    cudaGetSymbolAddress((void**)&pRq, gRq);
    cudaGetSymbolAddress((void**)&pRk, gRk);
    cudaGetSymbolAddress((void**)&pRv, gRv);
    cudaGetSymbolAddress((void**)&pAp, gAp);
    cudaGetSymbolAddress((void**)&pRp, gRp);
    cudaGetSymbolAddress((void**)&pTAp, gTAp);
    cudaGetSymbolAddress((void**)&pTRp, gTRp);
    cudaGetSymbolAddress((void**)&pWp, gWp);
    cudaGetSymbolAddress((void**)&pInvA, gInvA);
    cudaGetSymbolAddress((void**)&pInvR, gInvR);

    cudaFuncSetAttribute(gemm_fused_kernel<0>, cudaFuncAttributeMaxDynamicSharedMemorySize, GEMM_SMEM);
    cudaFuncSetAttribute(gemm_fused_kernel<1>, cudaFuncAttributeMaxDynamicSharedMemorySize, GEMM_SMEM);
    cudaFuncSetAttribute(gemm_fused_kernel<2>, cudaFuncAttributeMaxDynamicSharedMemorySize, GEMM_SMEM);
    cudaFuncSetAttribute(attn_mma_kernel, cudaFuncAttributeMaxDynamicSharedMemorySize, ATT_SMEM);

    // weight slot order: 0=W_lig_t 1=WQl 2=WKl 3=WVl 4=WOl | 5=W_res_t 6=WQr 7=WKr 8=WVr 9=WOr
    WIn win;
    win.w[0] = (const float*)d_in[2];
    win.w[1] = (const float*)d_in[4];
    win.w[2] = (const float*)d_in[5];
    win.w[3] = (const float*)d_in[6];
    win.w[4] = (const float*)d_in[7];
    win.w[5] = (const float*)d_in[3];
    win.w[6] = (const float*)d_in[8];
    win.w[7] = (const float*)d_in[9];
    win.w[8] = (const float*)d_in[10];
    win.w[9] = (const float*)d_in[11];

    const int aTiles = (nA + 127) / 128;
    const int rTiles = (nR + 127) / 128;
    const int totTiles = aTiles + rTiles;
    const int WSLOT = DD * DD * 2;   // 131072 floats per permuted weight slot

    fill_inv_kernel<<<256, 256>>>(lig, res);
    presplit_w_kernel<<<(10 * DD * DD + 255) / 256, 256>>>(win, pWp);
    // permuted-split input features (into the TA/TR permuted buffers, free at this point)
    splitperm_x_kernel<<<(nA * DD + 255) / 256, 256>>>(fatoms, pTAp, nA);
    splitperm_x_kernel<<<(nR * DD + 255) / 256, 256>>>(fres,   pTRp, nR);

    // init transforms: A0 = leaky(fatoms@W_lig_t), R0 = leaky(fres@W_res_t)
    GArgs gi = {};
    gi.Xp[0] = pTAp; gi.Xp[1] = pTRp;
    gi.Wp[0][0] = pWp + 0 * WSLOT; gi.Wp[1][0] = pWp + 5 * WSLOT;
    gi.Craw[0][0] = pA; gi.Craw[1][0] = pR;
    gi.Cp[0] = pAp; gi.Cp[1] = pRp;
    gi.M[0] = nA; gi.M[1] = nR; gi.aTiles = aTiles;

    // fused QKV projections
    GArgs gq = {};
    gq.Xp[0] = pAp; gq.Xp[1] = pRp;
    for (int j = 0; j < 3; j++) {
        gq.Wp[0][j] = pWp + (1 + j) * WSLOT;
        gq.Wp[1][j] = pWp + (6 + j) * WSLOT;
    }
    gq.Craw[0][0] = pAq; gq.Craw[0][1] = pAk; gq.Craw[0][2] = pAv;
    gq.Craw[1][0] = pRq; gq.Craw[1][1] = pRk; gq.Craw[1][2] = pRv;
    gq.M[0] = nA; gq.M[1] = nR; gq.aTiles = aTiles;

    // output GEMMs: A = leaky(TA@WOl)*invA + A ; R = leaky(TR@WOr)*invR + R
    GArgs go = {};
    go.Xp[0] = pTAp; go.Xp[1] = pTRp;
    go.Wp[0][0] = pWp + 4 * WSLOT; go.Wp[1][0] = pWp + 9 * WSLOT;
    go.Craw[0][0] = pA; go.Craw[1][0] = pR;
    go.Cp[0] = pAp; go.Cp[1] = pRp;
    go.scale[0] = pInvA; go.scale[1] = pInvR;
    go.base[0] = pA; go.base[1] = pR;
    go.M[0] = nA; go.M[1] = nR; go.aTiles = aTiles;

    gemm_fused_kernel<1><<<dim3(4, totTiles), 256, GEMM_SMEM>>>(gi);

    for (int it = 0; it < 3; it++) {
        gemm_fused_kernel<0><<<dim3(12, totTiles), 256, GEMM_SMEM>>>(gq);

        // atoms attend to residues: Q=Aq (<=64 rows/complex), K/V = Rk/Rv
        attn_mma_kernel<<<dim3(256, 1), 256, ATT_SMEM>>>(pAq, pRk, pRv, pTAp, lig, res);
        // residues attend to atoms: Q=Rq (64-row chunks), K/V = Ak/Av
        attn_mma_kernel<<<dim3(256, 8), 256, ATT_SMEM>>>(pRq, pAk, pAv, pTRp, res, lig);

        gemm_fused_kernel<2><<<dim3(4, totTiles), 256, GEMM_SMEM>>>(go);
    }

    copy_out_kernel<<<1024, 256>>>((float*)d_out, nA, nR);
}

// round 6
// speedup vs baseline: 1.1385x; 1.1385x over previous
#include <cuda_runtime.h>
#include <cstdint>

#define DD 256
#define NA_MAX (64*256)
#define NR_MAX (512*256)

// ---------------- scratch state (device globals; no allocation) ----------------
__device__ __align__(16) float gA [NA_MAX*DD];
__device__ __align__(16) float gR [NR_MAX*DD];
__device__ __align__(16) float gAq[NA_MAX*DD];
__device__ __align__(16) float gAk[NA_MAX*DD];
__device__ __align__(16) float gAv[NA_MAX*DD];
__device__ __align__(16) float gRq[NR_MAX*DD];
__device__ __align__(16) float gRk[NR_MAX*DD];
__device__ __align__(16) float gRv[NR_MAX*DD];
__device__ __align__(16) float gTA[NA_MAX*DD];
__device__ __align__(16) float gTR[NR_MAX*DD];
__device__ __align__(16) float gWp[10*DD*DD*2];   // weights: fragment-major hi/lo
__device__ float gInvA[NA_MAX];
__device__ float gInvR[NR_MAX];

__device__ __forceinline__ float leaky_f(float x) { return x >= 0.f ? x : 0.1f * x; }
__device__ __forceinline__ float sigmoid_f(float x) {
    return __fdividef(1.f, 1.f + __expf(-x));
}
__device__ __forceinline__ float to_tf32(float x) {
    uint32_t u;
    asm("cvt.rna.tf32.f32 %0, %1;" : "=r"(u) : "f"(x));
    return __uint_as_float(u);
}
__device__ __forceinline__ void split_tf32(float x, float& hi, float& lo) {
    uint32_t u;
    asm("cvt.rna.tf32.f32 %0, %1;" : "=r"(u) : "f"(x));
    hi = __uint_as_float(u);
    float r = x - hi;
    uint32_t v;
    asm("cvt.rna.tf32.f32 %0, %1;" : "=r"(v) : "f"(r));
    lo = __uint_as_float(v);
}
__device__ __forceinline__ void mma_tf32(float* d, const uint32_t* a, const uint32_t* b) {
    asm volatile(
        "mma.sync.aligned.m16n8k8.row.col.f32.tf32.tf32.f32 "
        "{%0,%1,%2,%3}, {%4,%5,%6,%7}, {%8,%9}, {%0,%1,%2,%3};\n"
        : "+f"(d[0]), "+f"(d[1]), "+f"(d[2]), "+f"(d[3])
        : "r"(a[0]), "r"(a[1]), "r"(a[2]), "r"(a[3]), "r"(b[0]), "r"(b[1]));
}
__device__ __forceinline__ uint32_t smem_u32(const void* p) {
    return (uint32_t)__cvta_generic_to_shared(p);
}
__device__ __forceinline__ void cp16(uint32_t s, const void* g) {
    asm volatile("cp.async.cg.shared.global [%0], [%1], 16;\n" :: "r"(s), "l"(g));
}
__device__ __forceinline__ void cp_commit() { asm volatile("cp.async.commit_group;\n"); }
template <int N> __device__ __forceinline__ void cp_wait() {
    asm volatile("cp.async.wait_group %0;\n" :: "n"(N));
}

// ---------------- per-row 1/count scales ----------------
__global__ void fill_inv_kernel(const int* __restrict__ lig, const int* __restrict__ res) {
    int b = blockIdx.x;
    int as = lig[2*b], ac = lig[2*b+1];
    int rs = res[2*b], rc = res[2*b+1];
    float ia = 1.f / (float)rc;
    float ir = 1.f / (float)ac;
    for (int i = threadIdx.x; i < ac; i += blockDim.x) gInvA[as + i] = ia;
    for (int i = threadIdx.x; i < rc; i += blockDim.x) gInvR[rs + i] = ir;
}

// ---------------- weight presplit + permute (fragment-major hi/lo) ----------------
// Layout per (slot, coltile4, ktile8): 4096-float chunk, addressed
//   ((kk*8 + nf8)*32 + lane)*4 + {bh_k0, bh_k1, bl_k0, bl_k1}
struct WIn { const float* w[10]; };
__global__ void presplit_w_kernel(WIn win, float* __restrict__ wp) {
    int i = blockIdx.x * 256 + threadIdx.x;
    if (i >= 10 * DD * DD) return;
    int s = i >> 16, rem = i & 65535;
    int k = rem >> 8, n = rem & 255;
    float h, l;
    split_tf32(win.w[s][rem], h, l);
    int coltile = n >> 6, nf8 = (n >> 3) & 7, lq = n & 7;
    int ktile = k >> 5, kk = (k >> 3) & 3, lr = k & 3, khalf = (k >> 2) & 1;
    int lane = lq * 4 + lr;
    size_t base = ((size_t)((s * 4 + coltile) * 8 + ktile)) * 4096
                + (size_t)((kk * 8 + nf8) * 32 + lane) * 4;
    wp[base + khalf] = h;
    wp[base + 2 + khalf] = l;
}

// ---------------- fused 3xTF32 pipelined GEMM ----------------
// grid = (NW*4 variants, aTiles+rTiles). X raw row-major, W pre-split fragment-major.
// MODE 0: C = XW ; 1: C = leaky(XW) ; 2: C = leaky(XW)*scale[r] + base[r,c]
struct GArgs {
    const float* X[2];
    const float* Wp[2][3];     // slot bases in gWp
    float*       C[2][3];
    const float* scale[2];
    const float* base[2];
    int M[2];
    int aTiles;
};

#define GX_STR 36
#define GA_FLOATS (128*GX_STR)             // 4608
#define GB_FLOATS 4096
#define G_STAGE (GA_FLOATS + GB_FLOATS)    // 8704 floats
#define GEMM_SMEM (2*G_STAGE*4)            // 69632 B

template <int MODE>
__global__ void gemm_fused_kernel(GArgs g)
{
    extern __shared__ float smf[];
    const int side = (blockIdx.y >= g.aTiles) ? 1 : 0;
    const int rt = side ? blockIdx.y - g.aTiles : blockIdx.y;
    const int w = blockIdx.x >> 2, coltile = blockIdx.x & 3;
    const int col0 = coltile * 64;
    const int M = g.M[side];
    const int row0 = rt * 128;

    const float* X = g.X[side];
    const float* Wp = g.Wp[side][w] + (size_t)coltile * 32768;
    float* C = g.C[side][w];

    const int tid = threadIdx.x, lane = tid & 31, warp = tid >> 5;
    const int wm = warp >> 1, wn = warp & 1;
    const int lq = lane >> 2, lr = lane & 3;

    float* sX[2] = { smf,             smf + G_STAGE };
    float* sB[2] = { smf + GA_FLOATS, smf + G_STAGE + GA_FLOATS };

    float acc[2][4][4] = {};

    // stage k-tile 0
    {
        #pragma unroll
        for (int j = 0; j < 4; j++) {
            int idx = tid + 256 * j;
            int row = idx >> 3, ch = idx & 7;
            int grow = row0 + row; if (grow > M - 1) grow = M - 1;
            cp16(smem_u32(sX[0] + row * GX_STR + ch * 4), X + (size_t)grow * DD + ch * 4);
        }
        #pragma unroll
        for (int j = 0; j < 4; j++)
            cp16(smem_u32(sB[0] + (tid + 256 * j) * 4), Wp + (size_t)(tid + 256 * j) * 4);
        cp_commit();
    }

    for (int t = 0; t < 8; t++) {
        int buf = t & 1;
        if (t < 7) {
            int k0 = (t + 1) * 32;
            const float* Wn = Wp + (size_t)(t + 1) * 4096;
            #pragma unroll
            for (int j = 0; j < 4; j++) {
                int idx = tid + 256 * j;
                int row = idx >> 3, ch = idx & 7;
                int grow = row0 + row; if (grow > M - 1) grow = M - 1;
                cp16(smem_u32(sX[buf ^ 1] + row * GX_STR + ch * 4),
                     X + (size_t)grow * DD + k0 + ch * 4);
            }
            #pragma unroll
            for (int j = 0; j < 4; j++)
                cp16(smem_u32(sB[buf ^ 1] + (tid + 256 * j) * 4), Wn + (size_t)(tid + 256 * j) * 4);
            cp_commit();
            cp_wait<1>();
        } else {
            cp_wait<0>();
        }
        __syncthreads();

        #pragma unroll
        for (int kk = 0; kk < 4; kk++) {
            uint32_t ah[2][4], al[2][4];
            #pragma unroll
            for (int mf = 0; mf < 2; mf++) {
                const float* xb = sX[buf] + (wm * 32 + mf * 16 + lq) * GX_STR + kk * 8 + lr;
                float raw[4];
                raw[0] = xb[0]; raw[1] = xb[8 * GX_STR];
                raw[2] = xb[4]; raw[3] = xb[8 * GX_STR + 4];
                #pragma unroll
                for (int e = 0; e < 4; e++) {
                    float h, l;
                    split_tf32(raw[e], h, l);
                    ah[mf][e] = __float_as_uint(h);
                    al[mf][e] = __float_as_uint(l);
                }
            }
            float4 bv[4];
            #pragma unroll
            for (int nf = 0; nf < 4; nf++)
                bv[nf] = *(const float4*)(sB[buf] + (size_t)((kk * 8 + wn * 4 + nf) * 32 + lane) * 4);

            #pragma unroll
            for (int mf = 0; mf < 2; mf++) {
                #pragma unroll
                for (int nf = 0; nf < 4; nf++) {
                    const uint32_t* bq = (const uint32_t*)&bv[nf];
                    uint32_t bh[2] = { bq[0], bq[1] };
                    uint32_t bl[2] = { bq[2], bq[3] };
                    mma_tf32(acc[mf][nf], al[mf], bh);
                    mma_tf32(acc[mf][nf], ah[mf], bl);
                    mma_tf32(acc[mf][nf], ah[mf], bh);
                }
            }
        }
        __syncthreads();
    }

    // ---- epilogue: raw coalesced-ish stores only ----
    #pragma unroll
    for (int mf = 0; mf < 2; mf++) {
        #pragma unroll
        for (int i = 0; i < 4; i++) {
            int r = row0 + wm * 32 + mf * 16 + lq + ((i >= 2) ? 8 : 0);
            if (r >= M) continue;
            float sc = (MODE == 2) ? g.scale[side][r] : 0.f;
            #pragma unroll
            for (int nf = 0; nf < 4; nf++) {
                int c = col0 + wn * 32 + nf * 8 + lr * 2 + (i & 1);
                float v = acc[mf][nf][i];
                if (MODE == 1) v = leaky_f(v);
                if (MODE == 2) v = leaky_f(v) * sc + g.base[side][(size_t)r * DD + c];
                C[(size_t)r * DD + c] = v;
            }
        }
    }
}

// ---------------- mma sigmoid attention, cp.async pipelined, permuted Q ----------------
// Block: (complex b, 64-row query chunk). O[q,:] = sum_kv sigmoid(Q[q].K[kv]) * V[kv,:]
#define KV_STR 264
#define SSTR2 40
#define ATT_QP 0
#define ATT_SS 16384
#define ATT_RA (16384 + 64*SSTR2)
#define ATT_RB (ATT_RA + 2*32*KV_STR)
#define ATT_SMEM ((ATT_RB + 2*32*KV_STR) * 4)   // 210944 B

__device__ __forceinline__ void attn_stage_kv(const float* K, const float* V,
                                              float* regKb, float* regVb,
                                              size_t kv0, int t0, int kvc, int tid)
{
    #pragma unroll
    for (int i = 0; i < 8; i++) {
        int idx = tid + 256 * i;
        int row = idx >> 6, ch = idx & 63;
        int gr = t0 + row; if (gr > kvc - 1) gr = kvc - 1;   // clamp: masked later
        cp16(smem_u32(regKb + row * KV_STR + ch * 4), K + (kv0 + gr) * DD + ch * 4);
        cp16(smem_u32(regVb + row * KV_STR + ch * 4), V + (kv0 + gr) * DD + ch * 4);
    }
}

__global__ void attn_mma_kernel(const float* __restrict__ Q, const float* __restrict__ K,
                                const float* __restrict__ V, float* __restrict__ O,
                                const int* __restrict__ scQ, const int* __restrict__ scKV)
{
    extern __shared__ float smf[];
    float* Qp = smf + ATT_QP;
    float* sS = smf + ATT_SS;
    float* regK[2]; float* regV[2];
    regK[0] = smf + ATT_RA; regV[0] = regK[0] + 32 * KV_STR;
    regK[1] = smf + ATT_RB; regV[1] = regK[1] + 32 * KV_STR;
    float* Qraw = regK[0];

    const int b = blockIdx.x;
    const int qs0 = scQ[2*b], qc = scQ[2*b+1];
    const int kv0i = scKV[2*b], kvc = scKV[2*b+1];
    const int qbeg = blockIdx.y * 64;
    if (qbeg >= qc) return;
    const int qcnt = (qc - qbeg < 64) ? (qc - qbeg) : 64;

    const int tid = threadIdx.x, lane = tid & 31, warp = tid >> 5;
    const int lq = lane >> 2, lr = lane & 3;

    #pragma unroll
    for (int i = 0; i < 16; i++) {
        int idx = tid + 256 * i;
        int row = idx >> 6, ch = idx & 63;
        int gr = qbeg + row; if (gr > qc - 1) gr = qc - 1;
        cp16(smem_u32(Qraw + row * KV_STR + ch * 4), Q + (size_t)(qs0 + gr) * DD + ch * 4);
    }
    cp_commit();
    attn_stage_kv(K, V, regK[1], regV[1], (size_t)kv0i, 0, kvc, tid);
    cp_commit();

    cp_wait<1>();
    __syncthreads();

    {
        int mt = warp >> 1;
        #pragma unroll
        for (int i = 0; i < 16; i++) {
            int kk = (warp & 1) * 16 + i;
            const float* qb = Qraw + (mt * 16 + lq) * KV_STR + kk * 8 + lr;
            float4 v;
            v.x = to_tf32(qb[0]);
            v.y = to_tf32(qb[8 * KV_STR]);
            v.z = to_tf32(qb[4]);
            v.w = to_tf32(qb[8 * KV_STR + 4]);
            *(float4*)(Qp + ((size_t)(mt * 32 + kk) * 32 + lane) * 4) = v;
        }
    }
    __syncthreads();

    float o[4][4][4] = {};
    const int nT = (kvc + 31) >> 5;

    for (int t = 0; t < nT; t++) {
        int buf = (t & 1) ^ 1;
        if (t + 1 < nT) {
            attn_stage_kv(K, V, regK[buf ^ 1], regV[buf ^ 1], (size_t)kv0i, (t + 1) * 32, kvc, tid);
            cp_commit();
            cp_wait<1>();
        } else {
            cp_wait<0>();
        }
        __syncthreads();

        int klim = kvc - t * 32; if (klim > 32) klim = 32;

        {
            const int wm = warp >> 1, wn = warp & 1;
            const int m0 = wm * 16, n0 = wn * 16;
            float s[2][4] = {};
            #pragma unroll 4
            for (int kk = 0; kk < 32; kk++) {
                float4 qv = *(const float4*)(Qp + ((size_t)(wm * 32 + kk) * 32 + lane) * 4);
                uint32_t a[4] = { __float_as_uint(qv.x), __float_as_uint(qv.y),
                                  __float_as_uint(qv.z), __float_as_uint(qv.w) };
                uint32_t bb[2][2];
                #pragma unroll
                for (int nf = 0; nf < 2; nf++) {
                    const float* kp = regK[buf] + (n0 + nf * 8 + lq) * KV_STR + kk * 8 + lr;
                    bb[nf][0] = __float_as_uint(to_tf32(kp[0]));
                    bb[nf][1] = __float_as_uint(to_tf32(kp[4]));
                }
                mma_tf32(s[0], a, bb[0]);
                mma_tf32(s[1], a, bb[1]);
            }
            #pragma unroll
            for (int nf = 0; nf < 2; nf++)
                #pragma unroll
                for (int e = 0; e < 4; e++) {
                    int row = m0 + lq + ((e >= 2) ? 8 : 0);
                    int col = n0 + nf * 8 + lr * 2 + (e & 1);
                    float v = (col < klim) ? sigmoid_f(s[nf][e]) : 0.f;
                    sS[row * SSTR2 + col] = to_tf32(v);
                }
        }
        __syncthreads();

        {
            const int n0 = warp * 32;
            #pragma unroll
            for (int ks = 0; ks < 4; ks++) {
                uint32_t a[4][4], bb[4][2];
                #pragma unroll
                for (int mf = 0; mf < 4; mf++) {
                    const float* sp = sS + (mf * 16 + lq) * SSTR2 + ks * 8 + lr;
                    a[mf][0] = __float_as_uint(sp[0]);
                    a[mf][1] = __float_as_uint(sp[8 * SSTR2]);
                    a[mf][2] = __float_as_uint(sp[4]);
                    a[mf][3] = __float_as_uint(sp[8 * SSTR2 + 4]);
                }
                #pragma unroll
                for (int nf = 0; nf < 4; nf++) {
                    const float* vp = regV[buf] + (ks * 8 + lr) * KV_STR + n0 + nf * 8 + lq;
                    bb[nf][0] = __float_as_uint(to_tf32(vp[0]));
                    bb[nf][1] = __float_as_uint(to_tf32(vp[4 * KV_STR]));
                }
                #pragma unroll
                for (int mf = 0; mf < 4; mf++)
                    #pragma unroll
                    for (int nf = 0; nf < 4; nf++)
                        mma_tf32(o[mf][nf], a[mf], bb[nf]);
            }
        }
        __syncthreads();
    }

    // ---- store O raw (coalesced-ish) ----
    const int n0 = warp * 32;
    float* Obase = O + (size_t)(qs0 + qbeg) * DD;
    #pragma unroll
    for (int mf = 0; mf < 4; mf++)
        #pragma unroll
        for (int e = 0; e < 4; e++) {
            int row = mf * 16 + lq + ((e >= 2) ? 8 : 0);
            if (row >= qcnt) continue;
            #pragma unroll
            for (int nf = 0; nf < 4; nf++) {
                int col = n0 + nf * 8 + lr * 2 + (e & 1);
                Obase[(size_t)row * DD + col] = o[mf][nf][e];
            }
        }
}

// ---------------- final output: concat(A_flat, R_flat) ----------------
__global__ void copy_out_kernel(float* __restrict__ out, int nA, int nR) {
    size_t na4 = (size_t)nA * DD / 4;
    size_t tot = (size_t)(nA + nR) * DD / 4;
    const float4* a4 = (const float4*)gA;
    const float4* r4 = (const float4*)gR;
    for (size_t i = blockIdx.x * (size_t)blockDim.x + threadIdx.x; i < tot;
         i += (size_t)gridDim.x * blockDim.x) {
        ((float4*)out)[i] = (i < na4) ? a4[i] : r4[i - na4];
    }
}

// ---------------- host launch ----------------
extern "C" void kernel_launch(void* const* d_in, const int* in_sizes, int n_in,
                              void* d_out, int out_size) {
    const float* fatoms = (const float*)d_in[0];
    const float* fres   = (const float*)d_in[1];
    const int* lig = (const int*)d_in[12];
    const int* res = (const int*)d_in[13];

    int nA = in_sizes[0] / DD;
    int nR = in_sizes[1] / DD;

    float *pA, *pR, *pAq, *pAk, *pAv, *pRq, *pRk, *pRv, *pTA, *pTR, *pWp, *pInvA, *pInvR;
    cudaGetSymbolAddress((void**)&pA,  gA);
    cudaGetSymbolAddress((void**)&pR,  gR);
    cudaGetSymbolAddress((void**)&pAq, gAq);
    cudaGetSymbolAddress((void**)&pAk, gAk);
    cudaGetSymbolAddress((void**)&pAv, gAv);
    cudaGetSymbolAddress((void**)&pRq, gRq);
    cudaGetSymbolAddress((void**)&pRk, gRk);
    cudaGetSymbolAddress((void**)&pRv, gRv);
    cudaGetSymbolAddress((void**)&pTA, gTA);
    cudaGetSymbolAddress((void**)&pTR, gTR);
    cudaGetSymbolAddress((void**)&pWp, gWp);
    cudaGetSymbolAddress((void**)&pInvA, gInvA);
    cudaGetSymbolAddress((void**)&pInvR, gInvR);

    cudaFuncSetAttribute(gemm_fused_kernel<0>, cudaFuncAttributeMaxDynamicSharedMemorySize, GEMM_SMEM);
    cudaFuncSetAttribute(gemm_fused_kernel<1>, cudaFuncAttributeMaxDynamicSharedMemorySize, GEMM_SMEM);
    cudaFuncSetAttribute(gemm_fused_kernel<2>, cudaFuncAttributeMaxDynamicSharedMemorySize, GEMM_SMEM);
    cudaFuncSetAttribute(attn_mma_kernel, cudaFuncAttributeMaxDynamicSharedMemorySize, ATT_SMEM);

    // weight slot order: 0=W_lig_t 1=WQl 2=WKl 3=WVl 4=WOl | 5=W_res_t 6=WQr 7=WKr 8=WVr 9=WOr
    WIn win;
    win.w[0] = (const float*)d_in[2];
    win.w[1] = (const float*)d_in[4];
    win.w[2] = (const float*)d_in[5];
    win.w[3] = (const float*)d_in[6];
    win.w[4] = (const float*)d_in[7];
    win.w[5] = (const float*)d_in[3];
    win.w[6] = (const float*)d_in[8];
    win.w[7] = (const float*)d_in[9];
    win.w[8] = (const float*)d_in[10];
    win.w[9] = (const float*)d_in[11];

    const int aTiles = (nA + 127) / 128;
    const int rTiles = (nR + 127) / 128;
    const int totTiles = aTiles + rTiles;
    const int WSLOT = DD * DD * 2;   // 131072 floats per permuted weight slot

    fill_inv_kernel<<<256, 256>>>(lig, res);
    presplit_w_kernel<<<(10 * DD * DD + 255) / 256, 256>>>(win, pWp);

    // init transforms: A0 = leaky(fatoms@W_lig_t), R0 = leaky(fres@W_res_t)
    GArgs gi = {};
    gi.X[0] = fatoms; gi.X[1] = fres;
    gi.Wp[0][0] = pWp + 0 * WSLOT; gi.Wp[1][0] = pWp + 5 * WSLOT;
    gi.C[0][0] = pA; gi.C[1][0] = pR;
    gi.M[0] = nA; gi.M[1] = nR; gi.aTiles = aTiles;

    // fused QKV projections
    GArgs gq = {};
    gq.X[0] = pA; gq.X[1] = pR;
    for (int j = 0; j < 3; j++) {
        gq.Wp[0][j] = pWp + (1 + j) * WSLOT;
        gq.Wp[1][j] = pWp + (6 + j) * WSLOT;
    }
    gq.C[0][0] = pAq; gq.C[0][1] = pAk; gq.C[0][2] = pAv;
    gq.C[1][0] = pRq; gq.C[1][1] = pRk; gq.C[1][2] = pRv;
    gq.M[0] = nA; gq.M[1] = nR; gq.aTiles = aTiles;

    // output GEMMs: A = leaky(TA@WOl)*invA + A ; R = leaky(TR@WOr)*invR + R
    GArgs go = {};
    go.X[0] = pTA; go.X[1] = pTR;
    go.Wp[0][0] = pWp + 4 * WSLOT; go.Wp[1][0] = pWp + 9 * WSLOT;
    go.C[0][0] = pA; go.C[1][0] = pR;
    go.scale[0] = pInvA; go.scale[1] = pInvR;
    go.base[0] = pA; go.base[1] = pR;
    go.M[0] = nA; go.M[1] = nR; go.aTiles = aTiles;

    gemm_fused_kernel<1><<<dim3(4, totTiles), 256, GEMM_SMEM>>>(gi);

    for (int it = 0; it < 3; it++) {
        gemm_fused_kernel<0><<<dim3(12, totTiles), 256, GEMM_SMEM>>>(gq);

        // atoms attend to residues: Q=Aq (<=64 rows/complex), K/V = Rk/Rv
        attn_mma_kernel<<<dim3(256, 1), 256, ATT_SMEM>>>(pAq, pRk, pRv, pTA, lig, res);
        // residues attend to atoms: Q=Rq (64-row chunks), K/V = Ak/Av
        attn_mma_kernel<<<dim3(256, 8), 256, ATT_SMEM>>>(pRq, pAk, pAv, pTR, res, lig);

        gemm_fused_kernel<2><<<dim3(4, totTiles), 256, GEMM_SMEM>>>(go);
    }

    copy_out_kernel<<<1024, 256>>>((float*)d_out, nA, nR);
}

// round 7
// speedup vs baseline: 1.6658x; 1.4631x over previous
#include <cuda_runtime.h>
#include <cstdint>

#define DD 256
#define NA_MAX (64*256)
#define NR_MAX (512*256)

// ---------------- scratch state (device globals; no allocation) ----------------
__device__ __align__(16) float gA [NA_MAX*DD];
__device__ __align__(16) float gR [NR_MAX*DD];
__device__ __align__(16) float gAq[NA_MAX*DD];
__device__ __align__(16) float gAk[NA_MAX*DD];
__device__ __align__(16) float gAv[NA_MAX*DD];
__device__ __align__(16) float gRq[NR_MAX*DD];
__device__ __align__(16) float gRk[NR_MAX*DD];
__device__ __align__(16) float gRv[NR_MAX*DD];
__device__ __align__(16) float gTA[NA_MAX*DD];
__device__ __align__(16) float gTR[NR_MAX*DD];
__device__ __align__(16) float gWp [10*DD*DD*2];  // weights: fragment-major hi/lo (3x path)
__device__ __align__(16) float gWp1[10*DD*DD];    // weights: fragment-major hi only (1x path)
__device__ float gInvA[NA_MAX];
__device__ float gInvR[NR_MAX];

__device__ __forceinline__ float leaky_f(float x) { return x >= 0.f ? x : 0.1f * x; }
__device__ __forceinline__ float sigmoid_f(float x) {
    return __fdividef(1.f, 1.f + __expf(-x));
}
__device__ __forceinline__ float to_tf32(float x) {
    uint32_t u;
    asm("cvt.rna.tf32.f32 %0, %1;" : "=r"(u) : "f"(x));
    return __uint_as_float(u);
}
__device__ __forceinline__ void split_tf32(float x, float& hi, float& lo) {
    uint32_t u;
    asm("cvt.rna.tf32.f32 %0, %1;" : "=r"(u) : "f"(x));
    hi = __uint_as_float(u);
    float r = x - hi;
    uint32_t v;
    asm("cvt.rna.tf32.f32 %0, %1;" : "=r"(v) : "f"(r));
    lo = __uint_as_float(v);
}
__device__ __forceinline__ void mma_tf32(float* d, const uint32_t* a, const uint32_t* b) {
    asm volatile(
        "mma.sync.aligned.m16n8k8.row.col.f32.tf32.tf32.f32 "
        "{%0,%1,%2,%3}, {%4,%5,%6,%7}, {%8,%9}, {%0,%1,%2,%3};\n"
        : "+f"(d[0]), "+f"(d[1]), "+f"(d[2]), "+f"(d[3])
        : "r"(a[0]), "r"(a[1]), "r"(a[2]), "r"(a[3]), "r"(b[0]), "r"(b[1]));
}
__device__ __forceinline__ uint32_t smem_u32(const void* p) {
    return (uint32_t)__cvta_generic_to_shared(p);
}
__device__ __forceinline__ void cp16(uint32_t s, const void* g) {
    asm volatile("cp.async.cg.shared.global [%0], [%1], 16;\n" :: "r"(s), "l"(g));
}
__device__ __forceinline__ void cp_commit() { asm volatile("cp.async.commit_group;\n"); }
template <int N> __device__ __forceinline__ void cp_wait() {
    asm volatile("cp.async.wait_group %0;\n" :: "n"(N));
}

// ---------------- per-row 1/count scales ----------------
__global__ void fill_inv_kernel(const int* __restrict__ lig, const int* __restrict__ res) {
    int b = blockIdx.x;
    int as = lig[2*b], ac = lig[2*b+1];
    int rs = res[2*b], rc = res[2*b+1];
    float ia = 1.f / (float)rc;
    float ir = 1.f / (float)ac;
    for (int i = threadIdx.x; i < ac; i += blockDim.x) gInvA[as + i] = ia;
    for (int i = threadIdx.x; i < rc; i += blockDim.x) gInvR[rs + i] = ir;
}

// ---------------- weight presplit + permute (fragment-major) ----------------
// 3x layout per (slot,coltile,ktile): 4096-float chunk  ((kk*8+nf8)*32+lane)*4 + {bh0,bh1,bl0,bl1}
// 1x layout per (slot,coltile,ktile): 2048-float chunk  ((kk*8+nf8)*32+lane)*2 + {bh0,bh1}
struct WIn { const float* w[10]; };
__global__ void presplit_w_kernel(WIn win, float* __restrict__ wp, float* __restrict__ wp1) {
    int i = blockIdx.x * 256 + threadIdx.x;
    if (i >= 10 * DD * DD) return;
    int s = i >> 16, rem = i & 65535;
    int k = rem >> 8, n = rem & 255;
    float h, l;
    split_tf32(win.w[s][rem], h, l);
    int coltile = n >> 6, nf8 = (n >> 3) & 7, lq = n & 7;
    int ktile = k >> 5, kk = (k >> 3) & 3, lr = k & 3, khalf = (k >> 2) & 1;
    int lane = lq * 4 + lr;
    int chunk = (s * 4 + coltile) * 8 + ktile;
    int fr = (kk * 8 + nf8) * 32 + lane;
    size_t b3 = (size_t)chunk * 4096 + (size_t)fr * 4;
    wp[b3 + khalf] = h;
    wp[b3 + 2 + khalf] = l;
    size_t b1 = (size_t)chunk * 2048 + (size_t)fr * 2;
    wp1[b1 + khalf] = h;
}

// ---------------- fused tf32 pipelined GEMM (PREC = 3x or 1x) ----------------
// grid = (NW*4 variants, aTiles+rTiles). X raw row-major, W pre-split fragment-major.
// MODE 0: C = XW ; 1: C = leaky(XW) ; 2: C = leaky(XW)*scale[r] + base[r,c]
struct GArgs {
    const float* X[2];
    const float* Wp[2][3];     // slot bases (in gWp for PREC=3, gWp1 for PREC=1)
    float*       C[2][3];
    const float* scale[2];
    const float* base[2];
    int M[2];
    int aTiles;
};

#define GX_STR 36
#define GA_FLOATS (128*GX_STR)             // 4608

template <int MODE, int PREC>
__global__ void gemm_fused_kernel(GArgs g)
{
    constexpr int BKT = (PREC == 3) ? 4096 : 2048;      // B floats per k-tile
    constexpr int STAGE = GA_FLOATS + BKT;
    extern __shared__ float smf[];
    const int side = (blockIdx.y >= g.aTiles) ? 1 : 0;
    const int rt = side ? blockIdx.y - g.aTiles : blockIdx.y;
    const int w = blockIdx.x >> 2, coltile = blockIdx.x & 3;
    const int col0 = coltile * 64;
    const int M = g.M[side];
    const int row0 = rt * 128;

    const float* X = g.X[side];
    const float* Wp = g.Wp[side][w] + (size_t)coltile * (8 * BKT);
    float* C = g.C[side][w];

    const int tid = threadIdx.x, lane = tid & 31, warp = tid >> 5;
    const int wm = warp >> 1, wn = warp & 1;
    const int lq = lane >> 2, lr = lane & 3;

    float* sX[2] = { smf,             smf + STAGE };
    float* sB[2] = { smf + GA_FLOATS, smf + STAGE + GA_FLOATS };

    float acc[2][4][4] = {};

    // stage k-tile 0
    {
        #pragma unroll
        for (int j = 0; j < 4; j++) {
            int idx = tid + 256 * j;
            int row = idx >> 3, ch = idx & 7;
            int grow = row0 + row; if (grow > M - 1) grow = M - 1;
            cp16(smem_u32(sX[0] + row * GX_STR + ch * 4), X + (size_t)grow * DD + ch * 4);
        }
        #pragma unroll
        for (int j = 0; j < BKT / 1024; j++)
            cp16(smem_u32(sB[0] + (tid + 256 * j) * 4), Wp + (size_t)(tid + 256 * j) * 4);
        cp_commit();
    }

    for (int t = 0; t < 8; t++) {
        int buf = t & 1;
        if (t < 7) {
            int k0 = (t + 1) * 32;
            const float* Wn = Wp + (size_t)(t + 1) * BKT;
            #pragma unroll
            for (int j = 0; j < 4; j++) {
                int idx = tid + 256 * j;
                int row = idx >> 3, ch = idx & 7;
                int grow = row0 + row; if (grow > M - 1) grow = M - 1;
                cp16(smem_u32(sX[buf ^ 1] + row * GX_STR + ch * 4),
                     X + (size_t)grow * DD + k0 + ch * 4);
            }
            #pragma unroll
            for (int j = 0; j < BKT / 1024; j++)
                cp16(smem_u32(sB[buf ^ 1] + (tid + 256 * j) * 4), Wn + (size_t)(tid + 256 * j) * 4);
            cp_commit();
            cp_wait<1>();
        } else {
            cp_wait<0>();
        }
        __syncthreads();

        #pragma unroll
        for (int kk = 0; kk < 4; kk++) {
            uint32_t ah[2][4], al[2][4];
            #pragma unroll
            for (int mf = 0; mf < 2; mf++) {
                const float* xb = sX[buf] + (wm * 32 + mf * 16 + lq) * GX_STR + kk * 8 + lr;
                float raw[4];
                raw[0] = xb[0]; raw[1] = xb[8 * GX_STR];
                raw[2] = xb[4]; raw[3] = xb[8 * GX_STR + 4];
                #pragma unroll
                for (int e = 0; e < 4; e++) {
                    if (PREC == 3) {
                        float h, l;
                        split_tf32(raw[e], h, l);
                        ah[mf][e] = __float_as_uint(h);
                        al[mf][e] = __float_as_uint(l);
                    } else {
                        ah[mf][e] = __float_as_uint(to_tf32(raw[e]));
                    }
                }
            }
            #pragma unroll
            for (int nf = 0; nf < 4; nf++) {
                if (PREC == 3) {
                    float4 bv = *(const float4*)(sB[buf] + (size_t)((kk * 8 + wn * 4 + nf) * 32 + lane) * 4);
                    const uint32_t* bq = (const uint32_t*)&bv;
                    uint32_t bh[2] = { bq[0], bq[1] };
                    uint32_t bl[2] = { bq[2], bq[3] };
                    #pragma unroll
                    for (int mf = 0; mf < 2; mf++) {
                        mma_tf32(acc[mf][nf], al[mf], bh);
                        mma_tf32(acc[mf][nf], ah[mf], bl);
                        mma_tf32(acc[mf][nf], ah[mf], bh);
                    }
                } else {
                    float2 bv = *(const float2*)(sB[buf] + (size_t)((kk * 8 + wn * 4 + nf) * 32 + lane) * 2);
                    uint32_t bh[2] = { __float_as_uint(bv.x), __float_as_uint(bv.y) };
                    #pragma unroll
                    for (int mf = 0; mf < 2; mf++)
                        mma_tf32(acc[mf][nf], ah[mf], bh);
                }
            }
        }
        __syncthreads();
    }

    // ---- epilogue ----
    #pragma unroll
    for (int mf = 0; mf < 2; mf++) {
        #pragma unroll
        for (int i = 0; i < 4; i++) {
            int r = row0 + wm * 32 + mf * 16 + lq + ((i >= 2) ? 8 : 0);
            if (r >= M) continue;
            float sc = (MODE == 2) ? g.scale[side][r] : 0.f;
            #pragma unroll
            for (int nf = 0; nf < 4; nf++) {
                int c = col0 + wn * 32 + nf * 8 + lr * 2 + (i & 1);
                float v = acc[mf][nf][i];
                if (MODE == 1) v = leaky_f(v);
                if (MODE == 2) v = leaky_f(v) * sc + g.base[side][(size_t)r * DD + c];
                C[(size_t)r * DD + c] = v;
            }
        }
    }
}

#define GEMM_SMEM3 (2*(GA_FLOATS + 4096)*4)
#define GEMM_SMEM1 (2*(GA_FLOATS + 2048)*4)

// ---------------- mma sigmoid attention, cp.async pipelined, permuted Q ----------------
#define KV_STR 264
#define SSTR2 40
#define ATT_QP 0
#define ATT_SS 16384
#define ATT_RA (16384 + 64*SSTR2)
#define ATT_RB (ATT_RA + 2*32*KV_STR)
#define ATT_SMEM ((ATT_RB + 2*32*KV_STR) * 4)   // 210944 B

__device__ __forceinline__ void attn_stage_kv(const float* K, const float* V,
                                              float* regKb, float* regVb,
                                              size_t kv0, int t0, int kvc, int tid)
{
    #pragma unroll
    for (int i = 0; i < 8; i++) {
        int idx = tid + 256 * i;
        int row = idx >> 6, ch = idx & 63;
        int gr = t0 + row; if (gr > kvc - 1) gr = kvc - 1;   // clamp: masked later
        cp16(smem_u32(regKb + row * KV_STR + ch * 4), K + (kv0 + gr) * DD + ch * 4);
        cp16(smem_u32(regVb + row * KV_STR + ch * 4), V + (kv0 + gr) * DD + ch * 4);
    }
}

__global__ void attn_mma_kernel(const float* __restrict__ Q, const float* __restrict__ K,
                                const float* __restrict__ V, float* __restrict__ O,
                                const int* __restrict__ scQ, const int* __restrict__ scKV)
{
    extern __shared__ float smf[];
    float* Qp = smf + ATT_QP;
    float* sS = smf + ATT_SS;
    float* regK[2]; float* regV[2];
    regK[0] = smf + ATT_RA; regV[0] = regK[0] + 32 * KV_STR;
    regK[1] = smf + ATT_RB; regV[1] = regK[1] + 32 * KV_STR;
    float* Qraw = regK[0];

    const int b = blockIdx.x;
    const int qs0 = scQ[2*b], qc = scQ[2*b+1];
    const int kv0i = scKV[2*b], kvc = scKV[2*b+1];
    const int qbeg = blockIdx.y * 64;
    if (qbeg >= qc) return;
    const int qcnt = (qc - qbeg < 64) ? (qc - qbeg) : 64;

    const int tid = threadIdx.x, lane = tid & 31, warp = tid >> 5;
    const int lq = lane >> 2, lr = lane & 3;

    #pragma unroll
    for (int i = 0; i < 16; i++) {
        int idx = tid + 256 * i;
        int row = idx >> 6, ch = idx & 63;
        int gr = qbeg + row; if (gr > qc - 1) gr = qc - 1;
        cp16(smem_u32(Qraw + row * KV_STR + ch * 4), Q + (size_t)(qs0 + gr) * DD + ch * 4);
    }
    cp_commit();
    attn_stage_kv(K, V, regK[1], regV[1], (size_t)kv0i, 0, kvc, tid);
    cp_commit();

    cp_wait<1>();
    __syncthreads();

    {
        int mt = warp >> 1;
        #pragma unroll
        for (int i = 0; i < 16; i++) {
            int kk = (warp & 1) * 16 + i;
            const float* qb = Qraw + (mt * 16 + lq) * KV_STR + kk * 8 + lr;
            float4 v;
            v.x = to_tf32(qb[0]);
            v.y = to_tf32(qb[8 * KV_STR]);
            v.z = to_tf32(qb[4]);
            v.w = to_tf32(qb[8 * KV_STR + 4]);
            *(float4*)(Qp + ((size_t)(mt * 32 + kk) * 32 + lane) * 4) = v;
        }
    }
    __syncthreads();

    float o[4][4][4] = {};
    const int nT = (kvc + 31) >> 5;

    for (int t = 0; t < nT; t++) {
        int buf = (t & 1) ^ 1;
        if (t + 1 < nT) {
            attn_stage_kv(K, V, regK[buf ^ 1], regV[buf ^ 1], (size_t)kv0i, (t + 1) * 32, kvc, tid);
            cp_commit();
            cp_wait<1>();
        } else {
            cp_wait<0>();
        }
        __syncthreads();

        int klim = kvc - t * 32; if (klim > 32) klim = 32;

        {
            const int wm = warp >> 1, wn = warp & 1;
            const int m0 = wm * 16, n0 = wn * 16;
            float s[2][4] = {};
            #pragma unroll 4
            for (int kk = 0; kk < 32; kk++) {
                float4 qv = *(const float4*)(Qp + ((size_t)(wm * 32 + kk) * 32 + lane) * 4);
                uint32_t a[4] = { __float_as_uint(qv.x), __float_as_uint(qv.y),
                                  __float_as_uint(qv.z), __float_as_uint(qv.w) };
                uint32_t bb[2][2];
                #pragma unroll
                for (int nf = 0; nf < 2; nf++) {
                    const float* kp = regK[buf] + (n0 + nf * 8 + lq) * KV_STR + kk * 8 + lr;
                    bb[nf][0] = __float_as_uint(to_tf32(kp[0]));
                    bb[nf][1] = __float_as_uint(to_tf32(kp[4]));
                }
                mma_tf32(s[0], a, bb[0]);
                mma_tf32(s[1], a, bb[1]);
            }
            #pragma unroll
            for (int nf = 0; nf < 2; nf++)
                #pragma unroll
                for (int e = 0; e < 4; e++) {
                    int row = m0 + lq + ((e >= 2) ? 8 : 0);
                    int col = n0 + nf * 8 + lr * 2 + (e & 1);
                    float v = (col < klim) ? sigmoid_f(s[nf][e]) : 0.f;
                    sS[row * SSTR2 + col] = to_tf32(v);
                }
        }
        __syncthreads();

        {
            const int n0 = warp * 32;
            #pragma unroll
            for (int ks = 0; ks < 4; ks++) {
                uint32_t a[4][4], bb[4][2];
                #pragma unroll
                for (int mf = 0; mf < 4; mf++) {
                    const float* sp = sS + (mf * 16 + lq) * SSTR2 + ks * 8 + lr;
                    a[mf][0] = __float_as_uint(sp[0]);
                    a[mf][1] = __float_as_uint(sp[8 * SSTR2]);
                    a[mf][2] = __float_as_uint(sp[4]);
                    a[mf][3] = __float_as_uint(sp[8 * SSTR2 + 4]);
                }
                #pragma unroll
                for (int nf = 0; nf < 4; nf++) {
                    const float* vp = regV[buf] + (ks * 8 + lr) * KV_STR + n0 + nf * 8 + lq;
                    bb[nf][0] = __float_as_uint(to_tf32(vp[0]));
                    bb[nf][1] = __float_as_uint(to_tf32(vp[4 * KV_STR]));
                }
                #pragma unroll
                for (int mf = 0; mf < 4; mf++)
                    #pragma unroll
                    for (int nf = 0; nf < 4; nf++)
                        mma_tf32(o[mf][nf], a[mf], bb[nf]);
            }
        }
        __syncthreads();
    }

    const int n0 = warp * 32;
    float* Obase = O + (size_t)(qs0 + qbeg) * DD;
    #pragma unroll
    for (int mf = 0; mf < 4; mf++)
        #pragma unroll
        for (int e = 0; e < 4; e++) {
            int row = mf * 16 + lq + ((e >= 2) ? 8 : 0);
            if (row >= qcnt) continue;
            #pragma unroll
            for (int nf = 0; nf < 4; nf++) {
                int col = n0 + nf * 8 + lr * 2 + (e & 1);
                Obase[(size_t)row * DD + col] = o[mf][nf][e];
            }
        }
}

// ---------------- final output: concat(A_flat, R_flat) ----------------
__global__ void copy_out_kernel(float* __restrict__ out, int nA, int nR) {
    size_t na4 = (size_t)nA * DD / 4;
    size_t tot = (size_t)(nA + nR) * DD / 4;
    const float4* a4 = (const float4*)gA;
    const float4* r4 = (const float4*)gR;
    for (size_t i = blockIdx.x * (size_t)blockDim.x + threadIdx.x; i < tot;
         i += (size_t)gridDim.x * blockDim.x) {
        ((float4*)out)[i] = (i < na4) ? a4[i] : r4[i - na4];
    }
}

// ---------------- host launch ----------------
extern "C" void kernel_launch(void* const* d_in, const int* in_sizes, int n_in,
                              void* d_out, int out_size) {
    const float* fatoms = (const float*)d_in[0];
    const float* fres   = (const float*)d_in[1];
    const int* lig = (const int*)d_in[12];
    const int* res = (const int*)d_in[13];

    int nA = in_sizes[0] / DD;
    int nR = in_sizes[1] / DD;

    float *pA, *pR, *pAq, *pAk, *pAv, *pRq, *pRk, *pRv, *pTA, *pTR;
    float *pWp, *pWp1, *pInvA, *pInvR;
    cudaGetSymbolAddress((void**)&pA,  gA);
    cudaGetSymbolAddress((void**)&pR,  gR);
    cudaGetSymbolAddress((void**)&pAq, gAq);
    cudaGetSymbolAddress((void**)&pAk, gAk);
    cudaGetSymbolAddress((void**)&pAv, gAv);
    cudaGetSymbolAddress((void**)&pRq, gRq);
    cudaGetSymbolAddress((void**)&pRk, gRk);
    cudaGetSymbolAddress((void**)&pRv, gRv);
    cudaGetSymbolAddress((void**)&pTA, gTA);
    cudaGetSymbolAddress((void**)&pTR, gTR);
    cudaGetSymbolAddress((void**)&pWp, gWp);
    cudaGetSymbolAddress((void**)&pWp1, gWp1);
    cudaGetSymbolAddress((void**)&pInvA, gInvA);
    cudaGetSymbolAddress((void**)&pInvR, gInvR);

    cudaFuncSetAttribute(gemm_fused_kernel<1,3>, cudaFuncAttributeMaxDynamicSharedMemorySize, GEMM_SMEM3);
    cudaFuncSetAttribute(gemm_fused_kernel<0,1>, cudaFuncAttributeMaxDynamicSharedMemorySize, GEMM_SMEM1);
    cudaFuncSetAttribute(gemm_fused_kernel<2,1>, cudaFuncAttributeMaxDynamicSharedMemorySize, GEMM_SMEM1);
    cudaFuncSetAttribute(attn_mma_kernel, cudaFuncAttributeMaxDynamicSharedMemorySize, ATT_SMEM);

    // weight slot order: 0=W_lig_t 1=WQl 2=WKl 3=WVl 4=WOl | 5=W_res_t 6=WQr 7=WKr 8=WVr 9=WOr
    WIn win;
    win.w[0] = (const float*)d_in[2];
    win.w[1] = (const float*)d_in[4];
    win.w[2] = (const float*)d_in[5];
    win.w[3] = (const float*)d_in[6];
    win.w[4] = (const float*)d_in[7];
    win.w[5] = (const float*)d_in[3];
    win.w[6] = (const float*)d_in[8];
    win.w[7] = (const float*)d_in[9];
    win.w[8] = (const float*)d_in[10];
    win.w[9] = (const float*)d_in[11];

    const int aTiles = (nA + 127) / 128;
    const int rTiles = (nR + 127) / 128;
    const int totTiles = aTiles + rTiles;
    const int WSLOT3 = DD * DD * 2;   // floats per slot, 3x layout
    const int WSLOT1 = DD * DD;       // floats per slot, 1x layout

    fill_inv_kernel<<<256, 256>>>(lig, res);
    presplit_w_kernel<<<(10 * DD * DD + 255) / 256, 256>>>(win, pWp, pWp1);

    // init transforms (3x): A0 = leaky(fatoms@W_lig_t), R0 = leaky(fres@W_res_t)
    GArgs gi = {};
    gi.X[0] = fatoms; gi.X[1] = fres;
    gi.Wp[0][0] = pWp + 0 * WSLOT3; gi.Wp[1][0] = pWp + 5 * WSLOT3;
    gi.C[0][0] = pA; gi.C[1][0] = pR;
    gi.M[0] = nA; gi.M[1] = nR; gi.aTiles = aTiles;

    // fused QKV projections (1x)
    GArgs gq = {};
    gq.X[0] = pA; gq.X[1] = pR;
    for (int j = 0; j < 3; j++) {
        gq.Wp[0][j] = pWp1 + (1 + j) * WSLOT1;
        gq.Wp[1][j] = pWp1 + (6 + j) * WSLOT1;
    }
    gq.C[0][0] = pAq; gq.C[0][1] = pAk; gq.C[0][2] = pAv;
    gq.C[1][0] = pRq; gq.C[1][1] = pRk; gq.C[1][2] = pRv;
    gq.M[0] = nA; gq.M[1] = nR; gq.aTiles = aTiles;

    // output GEMMs (1x): A = leaky(TA@WOl)*invA + A ; R = leaky(TR@WOr)*invR + R
    GArgs go = {};
    go.X[0] = pTA; go.X[1] = pTR;
    go.Wp[0][0] = pWp1 + 4 * WSLOT1; go.Wp[1][0] = pWp1 + 9 * WSLOT1;
    go.C[0][0] = pA; go.C[1][0] = pR;
    go.scale[0] = pInvA; go.scale[1] = pInvR;
    go.base[0] = pA; go.base[1] = pR;
    go.M[0] = nA; go.M[1] = nR; go.aTiles = aTiles;

    gemm_fused_kernel<1,3><<<dim3(4, totTiles), 256, GEMM_SMEM3>>>(gi);

    for (int it = 0; it < 3; it++) {
        gemm_fused_kernel<0,1><<<dim3(12, totTiles), 256, GEMM_SMEM1>>>(gq);

        // atoms attend to residues: Q=Aq (<=64 rows/complex), K/V = Rk/Rv
        attn_mma_kernel<<<dim3(256, 1), 256, ATT_SMEM>>>(pAq, pRk, pRv, pTA, lig, res);
        // residues attend to atoms: Q=Rq (64-row chunks), K/V = Ak/Av
        attn_mma_kernel<<<dim3(256, 8), 256, ATT_SMEM>>>(pRq, pAk, pAv, pTR, res, lig);

        gemm_fused_kernel<2,1><<<dim3(4, totTiles), 256, GEMM_SMEM1>>>(go);
    }

    copy_out_kernel<<<1024, 256>>>((float*)d_out, nA, nR);
}